// round 3
// baseline (speedup 1.0000x reference)
#include <cuda_runtime.h>
#include <stdint.h>

#define NN    20000
#define HALF  10000
#define EE    200000
#define PP    300
#define EPE   2000
#define KKEEP 16000
#define HS    4096
#define HM    4095
#define NB    8192     // select histogram bins

// ---------------- static device scratch (zero-initialized at load;
// every run restores the zero/clean invariant so graph replays are valid) ----
__device__ float4   g_h4[NN];
__device__ float    g_hp[NN * 3];
__device__ float    g_agg[NN * 3];
__device__ int      g_keys[PP * HS];    // 0 = empty, else node+1 (reset by k_member)
__device__ float4   g_mv[PP * HS];      // xyz: msum->mean ; w: cnt->arel (reset by k_member)
__device__ unsigned g_mm[PP * 2];       // per-pathway ukey min/max (re-init by k_hp)
__device__ unsigned g_ukey[PP * NN];
__device__ float4   g_xk[PP * NN];      // xyz: xk ; w: gate logit l
__device__ float    g_pathC[PP];

__device__ __forceinline__ unsigned fkey(float f) {
    unsigned u = __float_as_uint(f);
    return (u & 0x80000000u) ? ~u : (u | 0x80000000u);
}
__device__ __forceinline__ int hlookupG(int key, const int* __restrict__ keys) {
    unsigned slot = ((unsigned)key * 2654435761u) >> 20;
    int want = key + 1;
    for (;;) {
        int k2 = __ldg(&keys[slot]);
        if (k2 == want) return (int)slot;
        if (k2 == 0) return -1;
        slot = (slot + 1) & HM;
    }
}

// ---- packed f32x2 helpers (Blackwell) ----
typedef unsigned long long u64t;
__device__ __forceinline__ u64t pk2(float a, float b) {
    u64t r; asm("mov.b64 %0,{%1,%2};" : "=l"(r) : "f"(a), "f"(b)); return r;
}
__device__ __forceinline__ float2 upk2(u64t v) {
    float2 f; asm("mov.b64 {%0,%1},%2;" : "=f"(f.x), "=f"(f.y) : "l"(v)); return f;
}
__device__ __forceinline__ u64t fma2(u64t a, u64t b, u64t c) {
    u64t r; asm("fma.rn.f32x2 %0,%1,%2,%3;" : "=l"(r) : "l"(a), "l"(b), "l"(c)); return r;
}

// ---------------- global stage ----------------
__global__ void k_hp(const float* __restrict__ x, const float* __restrict__ Wp,
                     const float* __restrict__ bp) {
    int i = blockIdx.x * blockDim.x + threadIdx.x;
    if (i < 2 * PP) g_mm[i] = (i & 1) ? 0u : 0xffffffffu;   // [2p]=min, [2p+1]=max
    if (i >= NN) return;
    float x0 = x[3*i], x1 = x[3*i+1], x2 = x[3*i+2];
#pragma unroll
    for (int c = 0; c < 3; c++) {
        float v = fmaxf(bp[c] + x0*Wp[c] + x1*Wp[3+c] + x2*Wp[6+c], 0.f);
        g_hp[3*i+c] = v;
        g_agg[3*i+c] = v;
    }
}

__global__ void k_segmax(const int* __restrict__ ei) {
    int e = blockIdx.x * blockDim.x + threadIdx.x;
    if (e >= EE) return;
    int s = ei[e], d = ei[EE + e];
#pragma unroll
    for (int c = 0; c < 3; c++)
        atomicMax((int*)&g_agg[3*d+c], __float_as_int(g_hp[3*s+c]));
}

__global__ void k_h(const float* __restrict__ x, const float* __restrict__ Ws,
                    const float* __restrict__ Wn, const float* __restrict__ bc) {
    int i = blockIdx.x * blockDim.x + threadIdx.x;
    if (i >= NN) return;
    float x0 = x[3*i], x1 = x[3*i+1], x2 = x[3*i+2];
    float a0 = g_agg[3*i], a1 = g_agg[3*i+1], a2 = g_agg[3*i+2];
    float4 o;
    o.x = tanhf(bc[0] + x0*Ws[0] + x1*Ws[3] + x2*Ws[6] + a0*Wn[0] + a1*Wn[3] + a2*Wn[6]);
    o.y = tanhf(bc[1] + x0*Ws[1] + x1*Ws[4] + x2*Ws[7] + a0*Wn[1] + a1*Wn[4] + a2*Wn[7]);
    o.z = tanhf(bc[2] + x0*Ws[2] + x1*Ws[5] + x2*Ws[8] + a0*Wn[2] + a1*Wn[5] + a2*Wn[8]);
    o.w = 0.f;
    g_h4[i] = o;
}

// ---------------- stage 1: hash insert + msum/cnt ----------------
__global__ void __launch_bounds__(256) k_scatter1(const int* __restrict__ pe) {
    int p = blockIdx.x;
    const int* ps = pe + p * 2 * EPE;
    const int* pd = ps + EPE;
    int* keys = g_keys + p * HS;
    float* mvf = (float*)(g_mv + p * HS);
    for (int e = threadIdx.x; e < EPE; e += 256) {
        int s = ps[e], d = pd[e];
        unsigned slot = ((unsigned)d * 2654435761u) >> 20;
        for (;;) {
            int prev = atomicCAS(&keys[slot], 0, d + 1);
            if (prev == 0 || prev == d + 1) break;
            slot = (slot + 1) & HM;
        }
        float4 hv = g_h4[s];
        atomicAdd(&mvf[4*slot],   hv.x);
        atomicAdd(&mvf[4*slot+1], hv.y);
        atomicAdd(&mvf[4*slot+2], hv.z);
        atomicAdd(&mvf[4*slot+3], 1.f);
    }
}

// ---------------- stage 1b: msum/cnt -> mean, zero arel ----------------
__global__ void k_norm() {
    int idx = blockIdx.x * blockDim.x + threadIdx.x;
    if (idx >= PP * HS) return;
    if (g_keys[idx] != 0) {
        float4 v = g_mv[idx];
        float inv = 1.f / v.w;
        g_mv[idx] = make_float4(v.x * inv, v.y * inv, v.z * inv, 0.f);
    }
}

// ---------------- stage 2: arel[d] += xc(s) . Wrel ----------------
__global__ void __launch_bounds__(256) k_scatter2(
    const int* __restrict__ pe,
    const float* __restrict__ subWl, const float* __restrict__ subbl,
    const float* __restrict__ subWr, const float* __restrict__ pWrel) {
    int p = blockIdx.x;
    float Wl[9], Wr[9];
#pragma unroll
    for (int j = 0; j < 9; j++) { Wl[j] = __ldg(subWl + 9*p + j); Wr[j] = __ldg(subWr + 9*p + j); }
    float bl0 = __ldg(subbl+3*p), bl1 = __ldg(subbl+3*p+1), bl2 = __ldg(subbl+3*p+2);
    float wr0 = __ldg(pWrel+3*p), wr1 = __ldg(pWrel+3*p+1), wr2 = __ldg(pWrel+3*p+2);

    const int* ps = pe + p * 2 * EPE;
    const int* pd = ps + EPE;
    const int* keys = g_keys + p * HS;
    const float4* mv = g_mv + p * HS;
    float* mvf = (float*)(g_mv + p * HS);

    for (int e = threadIdx.x; e < EPE; e += 256) {
        int s = ps[e], d = pd[e];
        float4 hv = g_h4[s];
        float m0 = 0.f, m1 = 0.f, m2 = 0.f;
        int sl = hlookupG(s, keys);
        if (sl >= 0) { float4 mm = __ldg(&mv[sl]); m0 = mm.x; m1 = mm.y; m2 = mm.z; }
        float xc0 = fmaxf(bl0 + hv.x*Wr[0] + hv.y*Wr[3] + hv.z*Wr[6] + m0*Wl[0] + m1*Wl[3] + m2*Wl[6], 0.f);
        float xc1 = fmaxf(bl1 + hv.x*Wr[1] + hv.y*Wr[4] + hv.z*Wr[7] + m0*Wl[1] + m1*Wl[4] + m2*Wl[7], 0.f);
        float xc2 = fmaxf(bl2 + hv.x*Wr[2] + hv.y*Wr[5] + hv.z*Wr[8] + m0*Wl[2] + m1*Wl[5] + m2*Wl[8], 0.f);
        float val = xc0*wr0 + xc1*wr1 + xc2*wr2;
        int sd = hlookupG(d, keys);
        atomicAdd(&mvf[4*sd+3], val);
    }
}

// ---------------- stage 3: base score + xk/l for ALL nodes (non-member form) ----
__global__ void __launch_bounds__(256) k_score(
    const float* __restrict__ subWr, const float* __restrict__ subbl,
    const float* __restrict__ pWroot, const float* __restrict__ poolb,
    const float* __restrict__ gateW, const float* __restrict__ gateb) {
    __shared__ unsigned smn[8], smx[8];
    int p = blockIdx.y;
    int i = blockIdx.x * 256 + threadIdx.x;
    bool act = (i < HALF);
    int j = i + HALF;

    float Wr[9];
#pragma unroll
    for (int q = 0; q < 9; q++) Wr[q] = __ldg(subWr + 9*p + q);
    float bl0 = __ldg(subbl+3*p), bl1 = __ldg(subbl+3*p+1), bl2 = __ldg(subbl+3*p+2);
    float wo0 = __ldg(pWroot+3*p), wo1 = __ldg(pWroot+3*p+1), wo2 = __ldg(pWroot+3*p+2);
    float pb  = __ldg(poolb + p);
    float gW0 = __ldg(gateW+3*p), gW1 = __ldg(gateW+3*p+1), gW2 = __ldg(gateW+3*p+2);
    float gb  = __ldg(gateb + p);

    u64t w0 = pk2(Wr[0], Wr[0]), w1 = pk2(Wr[1], Wr[1]), w2 = pk2(Wr[2], Wr[2]);
    u64t w3 = pk2(Wr[3], Wr[3]), w4 = pk2(Wr[4], Wr[4]), w5 = pk2(Wr[5], Wr[5]);
    u64t w6 = pk2(Wr[6], Wr[6]), w7 = pk2(Wr[7], Wr[7]), w8 = pk2(Wr[8], Wr[8]);
    u64t b0 = pk2(bl0, bl0), b1 = pk2(bl1, bl1), b2 = pk2(bl2, bl2);

    unsigned mymin = 0xffffffffu, mymax = 0u;
    if (act) {
        float4 hA = g_h4[i];
        float4 hB = g_h4[j];
        u64t hx = pk2(hA.x, hB.x), hy = pk2(hA.y, hB.y), hz = pk2(hA.z, hB.z);
        u64t c0 = fma2(hx, w0, fma2(hy, w3, fma2(hz, w6, b0)));
        u64t c1 = fma2(hx, w1, fma2(hy, w4, fma2(hz, w7, b1)));
        u64t c2 = fma2(hx, w2, fma2(hy, w5, fma2(hz, w8, b2)));
        float2 f0 = upk2(c0), f1 = upk2(c1), f2 = upk2(c2);

        // node A
        {
            float xc0 = fmaxf(f0.x, 0.f), xc1 = fmaxf(f1.x, 0.f), xc2 = fmaxf(f2.x, 0.f);
            float sc = pb + xc0*wo0 + xc1*wo1 + xc2*wo2;
            unsigned u = fkey(sc);
            float e2 = __expf(2.f * sc);
            float tv = 1.f - 2.f / (e2 + 1.f);
            float k0 = xc0*tv, k1 = xc1*tv, k2 = xc2*tv;
            float l = gb + k0*gW0 + k1*gW1 + k2*gW2;
            g_ukey[p*NN + i] = u;
            g_xk[p*NN + i] = make_float4(k0, k1, k2, l);
            mymin = min(mymin, u); mymax = max(mymax, u);
        }
        // node B
        {
            float xc0 = fmaxf(f0.y, 0.f), xc1 = fmaxf(f1.y, 0.f), xc2 = fmaxf(f2.y, 0.f);
            float sc = pb + xc0*wo0 + xc1*wo1 + xc2*wo2;
            unsigned u = fkey(sc);
            float e2 = __expf(2.f * sc);
            float tv = 1.f - 2.f / (e2 + 1.f);
            float k0 = xc0*tv, k1 = xc1*tv, k2 = xc2*tv;
            float l = gb + k0*gW0 + k1*gW1 + k2*gW2;
            g_ukey[p*NN + j] = u;
            g_xk[p*NN + j] = make_float4(k0, k1, k2, l);
            mymin = min(mymin, u); mymax = max(mymax, u);
        }
    }
    // block min/max reduce -> 2 atomics
    mymin = __reduce_min_sync(0xffffffffu, mymin);
    mymax = __reduce_max_sync(0xffffffffu, mymax);
    int lane = threadIdx.x & 31, w = threadIdx.x >> 5;
    if (lane == 0) { smn[w] = mymin; smx[w] = mymax; }
    __syncthreads();
    if (threadIdx.x == 0) {
        unsigned mn = smn[0], mx = smx[0];
#pragma unroll
        for (int q = 1; q < 8; q++) { mn = min(mn, smn[q]); mx = max(mx, smx[q]); }
        atomicMin(&g_mm[2*p], mn);
        atomicMax(&g_mm[2*p+1], mx);
    }
}

// ---------------- stage 4: member correction + table cleanup ----------------
__global__ void __launch_bounds__(256) k_member(
    const float* __restrict__ subWl, const float* __restrict__ subbl,
    const float* __restrict__ subWr, const float* __restrict__ pWroot,
    const float* __restrict__ poolb,
    const float* __restrict__ gateW, const float* __restrict__ gateb) {
    __shared__ unsigned smn[8], smx[8];
    int p = blockIdx.x;
    float Wl[9], Wr[9];
#pragma unroll
    for (int q = 0; q < 9; q++) { Wl[q] = __ldg(subWl + 9*p + q); Wr[q] = __ldg(subWr + 9*p + q); }
    float bl0 = __ldg(subbl+3*p), bl1 = __ldg(subbl+3*p+1), bl2 = __ldg(subbl+3*p+2);
    float wo0 = __ldg(pWroot+3*p), wo1 = __ldg(pWroot+3*p+1), wo2 = __ldg(pWroot+3*p+2);
    float pb  = __ldg(poolb + p);
    float gW0 = __ldg(gateW+3*p), gW1 = __ldg(gateW+3*p+1), gW2 = __ldg(gateW+3*p+2);
    float gb  = __ldg(gateb + p);

    int* keys = g_keys + p * HS;
    float4* mv = g_mv + p * HS;
    unsigned mymin = 0xffffffffu, mymax = 0u;

    for (int slot = threadIdx.x; slot < HS; slot += 256) {
        int kk = keys[slot];
        if (kk != 0) {
            int d = kk - 1;
            float4 mm = mv[slot];
            float4 hv = g_h4[d];
            float xc0 = fmaxf(bl0 + hv.x*Wr[0] + hv.y*Wr[3] + hv.z*Wr[6] + mm.x*Wl[0] + mm.y*Wl[3] + mm.z*Wl[6], 0.f);
            float xc1 = fmaxf(bl1 + hv.x*Wr[1] + hv.y*Wr[4] + hv.z*Wr[7] + mm.x*Wl[1] + mm.y*Wl[4] + mm.z*Wl[7], 0.f);
            float xc2 = fmaxf(bl2 + hv.x*Wr[2] + hv.y*Wr[5] + hv.z*Wr[8] + mm.x*Wl[2] + mm.y*Wl[5] + mm.z*Wl[8], 0.f);
            float sc = pb + mm.w + xc0*wo0 + xc1*wo1 + xc2*wo2;
            unsigned u = fkey(sc);
            float e2 = __expf(2.f * sc);
            float tv = 1.f - 2.f / (e2 + 1.f);
            float k0 = xc0*tv, k1 = xc1*tv, k2 = xc2*tv;
            float l = gb + k0*gW0 + k1*gW1 + k2*gW2;
            g_ukey[p*NN + d] = u;
            g_xk[p*NN + d] = make_float4(k0, k1, k2, l);
            mymin = min(mymin, u); mymax = max(mymax, u);
            keys[slot] = 0;                          // restore clean state
            mv[slot] = make_float4(0.f, 0.f, 0.f, 0.f);
        }
    }
    mymin = __reduce_min_sync(0xffffffffu, mymin);
    mymax = __reduce_max_sync(0xffffffffu, mymax);
    int lane = threadIdx.x & 31, w = threadIdx.x >> 5;
    if (lane == 0) { smn[w] = mymin; smx[w] = mymax; }
    __syncthreads();
    if (threadIdx.x == 0) {
        unsigned mn = smn[0], mx = smx[0];
#pragma unroll
        for (int q = 1; q < 8; q++) { mn = min(mn, smn[q]); mx = max(mx, smx[q]); }
        atomicMin(&g_mm[2*p], mn);
        atomicMax(&g_mm[2*p+1], mx);
    }
}

// ---------------- stage 5: exact top-K select + fused softmax readout -------
__global__ void __launch_bounds__(1024) k_selrank(
    const float* __restrict__ linW, const float* __restrict__ linb,
    const float* __restrict__ mlpW) {
    __shared__ unsigned sh[NB];
    __shared__ unsigned sscan[1024];
    __shared__ unsigned s_bin, s_rem, s_cnt;
    const int p = blockIdx.x;
    const int tid = threadIdx.x;
    const int lane = tid & 31;
    const unsigned* uk = g_ukey + p * NN;

    unsigned lo = g_mm[2*p], hi = g_mm[2*p+1];
    unsigned rem = KKEEP, ceq = NN;

    while (lo < hi) {
        unsigned long long width = (unsigned long long)(hi - lo) + 1ull;
        int bits = 64 - __clzll((long long)(width - 1ull));
        int shift = bits > 13 ? bits - 13 : 0;
        for (int b = tid; b < NB; b += 1024) sh[b] = 0;
        __syncthreads();
        for (int i = tid; i < NN; i += 1024) {
            unsigned u = uk[i];
            unsigned bin = 0xffffffffu;
            if (u >= lo && u <= hi) bin = (u - lo) >> shift;
            unsigned msk = __match_any_sync(0xffffffffu, bin);
            if (bin != 0xffffffffu && (__ffs(msk) - 1) == lane)
                atomicAdd(&sh[bin], __popc(msk));
        }
        __syncthreads();
        unsigned psum = 0;
#pragma unroll
        for (int q = 0; q < NB/1024; q++) psum += sh[tid*(NB/1024)+q];
        sscan[tid] = psum; __syncthreads();
        for (int d = 1; d < 1024; d <<= 1) {
            unsigned v = sscan[tid] + ((tid + d < 1024) ? sscan[tid + d] : 0);
            __syncthreads(); sscan[tid] = v; __syncthreads();
        }
        unsigned c = (tid + 1 < 1024) ? sscan[tid + 1] : 0;   // sum of chunks above
        for (int q = NB/1024 - 1; q >= 0; q--) {
            int b = tid*(NB/1024) + q;
            unsigned hc = sh[b];
            if (c < rem && c + hc >= rem) { s_bin = b; s_cnt = hc; s_rem = rem - c; }
            c += hc;
        }
        __syncthreads();
        unsigned bin = s_bin; rem = s_rem; ceq = s_cnt;
        unsigned nlo = lo + (bin << shift);
        unsigned long long nhi64 = (unsigned long long)nlo + (1ull << shift) - 1ull;
        hi = (nhi64 > (unsigned long long)hi) ? hi : (unsigned)nhi64;
        lo = nlo;
        __syncthreads();
    }
    const unsigned Tu = lo;
    unsigned Itie = NN;   // keep-all-ties sentinel

    if (rem < ceq) {
        unsigned lo2 = 0, hi2 = NN - 1;
        while (lo2 < hi2) {
            unsigned long long width = (unsigned long long)(hi2 - lo2) + 1ull;
            int bits = 64 - __clzll((long long)(width - 1ull));
            int shift = bits > 13 ? bits - 13 : 0;
            for (int b = tid; b < NB; b += 1024) sh[b] = 0;
            __syncthreads();
            for (int i = tid; i < NN; i += 1024) {
                unsigned bin = 0xffffffffu;
                if (uk[i] == Tu && (unsigned)i >= lo2 && (unsigned)i <= hi2)
                    bin = ((unsigned)i - lo2) >> shift;
                unsigned msk = __match_any_sync(0xffffffffu, bin);
                if (bin != 0xffffffffu && (__ffs(msk) - 1) == lane)
                    atomicAdd(&sh[bin], __popc(msk));
            }
            __syncthreads();
            unsigned psum = 0;
#pragma unroll
            for (int q = 0; q < NB/1024; q++) psum += sh[tid*(NB/1024)+q];
            sscan[tid] = psum; __syncthreads();
            for (int d = 1; d < 1024; d <<= 1) {
                unsigned v = sscan[tid] + ((tid >= d) ? sscan[tid - d] : 0);
                __syncthreads(); sscan[tid] = v; __syncthreads();
            }
            unsigned c = sscan[tid] - psum;   // sum of chunks below (ascending)
            for (int q = 0; q < NB/1024; q++) {
                int b = tid*(NB/1024) + q;
                unsigned hc = sh[b];
                if (c < rem && c + hc >= rem) { s_bin = b; s_rem = rem - c; }
                c += hc;
            }
            __syncthreads();
            unsigned bin = s_bin; rem = s_rem;
            unsigned nlo = lo2 + (bin << shift);
            unsigned long long nhi64 = (unsigned long long)nlo + (1ull << shift) - 1ull;
            hi2 = (nhi64 > (unsigned long long)hi2) ? hi2 : (unsigned)nhi64;
            lo2 = nlo;
            __syncthreads();
        }
        Itie = lo2;
    }

    // fused softmax readout over kept nodes (constant-shift-free: l is O(1))
    float ssum = 0.f, a0 = 0.f, a1 = 0.f, a2 = 0.f;
    for (int i = tid; i < NN; i += 1024) {
        unsigned u = uk[i];
        bool kept = (u > Tu) || (u == Tu && (unsigned)i <= Itie);
        if (!kept) continue;
        float4 v = g_xk[p*NN + i];
        float e = __expf(v.w);
        ssum += e; a0 += e*v.x; a1 += e*v.y; a2 += e*v.z;
    }
#pragma unroll
    for (int off = 16; off > 0; off >>= 1) {
        ssum += __shfl_down_sync(0xffffffffu, ssum, off);
        a0   += __shfl_down_sync(0xffffffffu, a0, off);
        a1   += __shfl_down_sync(0xffffffffu, a1, off);
        a2   += __shfl_down_sync(0xffffffffu, a2, off);
    }
    __syncthreads();
    float* red = (float*)sh;
    int w = tid >> 5;
    if (lane == 0) { red[w] = ssum; red[32+w] = a0; red[64+w] = a1; red[96+w] = a2; }
    __syncthreads();
    if (tid == 0) {
        float S = 0.f, A0 = 0.f, A1 = 0.f, A2 = 0.f;
#pragma unroll
        for (int q = 0; q < 32; q++) { S += red[q]; A0 += red[32+q]; A1 += red[64+q]; A2 += red[96+q]; }
        float inv = 1.f / S;
        float v0 = fmaxf(A0 * inv, 0.f);
        float v1 = fmaxf(A1 * inv, 0.f);
        float v2 = fmaxf(A2 * inv, 0.f);
        float rr = fmaxf(v0 * linW[0] + v1 * linW[1] + v2 * linW[2] + linb[0], 0.f);
        g_pathC[p] = rr * mlpW[p];
    }
}

__global__ void k_out(const float* __restrict__ mlpb, float* __restrict__ out) {
    __shared__ float sbuf[256];
    int tid = threadIdx.x;
    float v = 0.f;
    for (int i = tid; i < PP; i += 256) v += g_pathC[i];
    sbuf[tid] = v;
    __syncthreads();
    for (int s = 128; s > 0; s >>= 1) { if (tid < s) sbuf[tid] += sbuf[tid + s]; __syncthreads(); }
    if (tid == 0) out[0] = 1.f / (1.f + expf(-(sbuf[0] + mlpb[0])));
}

// ---------------- launch ----------------
extern "C" void kernel_launch(void* const* d_in, const int* in_sizes, int n_in,
                              void* d_out, int out_size) {
    const float* x          = (const float*)d_in[0];
    const int*   edge_index = (const int*)  d_in[1];
    const int*   path_edges = (const int*)  d_in[2];
    const float* W_pool     = (const float*)d_in[3];
    const float* b_pool     = (const float*)d_in[4];
    const float* W_self     = (const float*)d_in[5];
    const float* W_neigh    = (const float*)d_in[6];
    const float* b_conv     = (const float*)d_in[7];
    const float* sub_Wl     = (const float*)d_in[8];
    const float* sub_bl     = (const float*)d_in[9];
    const float* sub_Wr     = (const float*)d_in[10];
    const float* pool_Wrel  = (const float*)d_in[11];
    const float* pool_Wroot = (const float*)d_in[12];
    const float* pool_b     = (const float*)d_in[13];
    const float* gate_W     = (const float*)d_in[14];
    const float* gate_b     = (const float*)d_in[15];
    const float* lin_W      = (const float*)d_in[16];
    const float* lin_b      = (const float*)d_in[17];
    const float* mlp_W      = (const float*)d_in[18];
    const float* mlp_b      = (const float*)d_in[19];
    float* out = (float*)d_out;

    k_hp      <<<(NN + 255) / 256, 256>>>(x, W_pool, b_pool);
    k_segmax  <<<(EE + 511) / 512, 512>>>(edge_index);
    k_h       <<<(NN + 255) / 256, 256>>>(x, W_self, W_neigh, b_conv);
    k_scatter1<<<PP, 256>>>(path_edges);
    k_norm    <<<(PP * HS + 255) / 256, 256>>>();
    k_scatter2<<<PP, 256>>>(path_edges, sub_Wl, sub_bl, sub_Wr, pool_Wrel);
    {
        dim3 grid((HALF + 255) / 256, PP);
        k_score<<<grid, 256>>>(sub_Wr, sub_bl, pool_Wroot, pool_b, gate_W, gate_b);
    }
    k_member  <<<PP, 256>>>(sub_Wl, sub_bl, sub_Wr, pool_Wroot, pool_b, gate_W, gate_b);
    k_selrank <<<PP, 1024>>>(lin_W, lin_b, mlp_W);
    k_out     <<<1, 256>>>(mlp_b, out);
}

// round 4
// speedup vs baseline: 1.4341x; 1.4341x over previous
#include <cuda_runtime.h>
#include <stdint.h>

#define NN    20000
#define EE    200000
#define PP    300
#define EPE   2000
#define KKEEP 16000
#define HS    4096
#define HM    4095
#define NB    8192
#define NT    1024
#define NITER 20        // ceil(NN/NT) uniform trip count

// dynamic smem layout (bytes):
//   ukey : 20000 u32            [0,      80000)
//   keysh: 4096  int            [80000,  96384)
//   mv   : 4096  float4         [96384, 161920)
//   hist : 8192  u32            [161920,194688)
//   sscan: 1024  u32            [194688,198784)
#define SMEM_BYTES 198784

__device__ float4 g_h4[NN];
__device__ float  g_hp[NN * 3];
__device__ float  g_agg[NN * 3];
__device__ float  g_pathC[PP];

__device__ __forceinline__ unsigned fkey(float f) {
    unsigned u = __float_as_uint(f);
    return (u & 0x80000000u) ? ~u : (u | 0x80000000u);
}
__device__ __forceinline__ float unfkey(unsigned u) {
    return __uint_as_float((u & 0x80000000u) ? (u & 0x7fffffffu) : ~u);
}
__device__ __forceinline__ int hlookupS(int key, const int* keys) {
    unsigned slot = ((unsigned)key * 2654435761u) >> 20;
    int want = key + 1;
    for (;;) {
        int k2 = keys[slot];
        if (k2 == want) return (int)slot;
        if (k2 == 0) return -1;
        slot = (slot + 1) & HM;
    }
}

// ---------------- global stage ----------------
__global__ void k_hp(const float* __restrict__ x, const float* __restrict__ Wp,
                     const float* __restrict__ bp) {
    int i = blockIdx.x * blockDim.x + threadIdx.x;
    if (i >= NN) return;
    float x0 = x[3*i], x1 = x[3*i+1], x2 = x[3*i+2];
#pragma unroll
    for (int c = 0; c < 3; c++) {
        float v = fmaxf(bp[c] + x0*Wp[c] + x1*Wp[3+c] + x2*Wp[6+c], 0.f);
        g_hp[3*i+c] = v;
        g_agg[3*i+c] = v;
    }
}

__global__ void k_segmax(const int* __restrict__ ei) {
    int e = blockIdx.x * blockDim.x + threadIdx.x;
    if (e >= EE) return;
    int s = ei[e], d = ei[EE + e];
#pragma unroll
    for (int c = 0; c < 3; c++)
        atomicMax((int*)&g_agg[3*d+c], __float_as_int(g_hp[3*s+c]));
}

__global__ void k_h(const float* __restrict__ x, const float* __restrict__ Ws,
                    const float* __restrict__ Wn, const float* __restrict__ bc) {
    int i = blockIdx.x * blockDim.x + threadIdx.x;
    if (i >= NN) return;
    float x0 = x[3*i], x1 = x[3*i+1], x2 = x[3*i+2];
    float a0 = g_agg[3*i], a1 = g_agg[3*i+1], a2 = g_agg[3*i+2];
    float4 o;
    o.x = tanhf(bc[0] + x0*Ws[0] + x1*Ws[3] + x2*Ws[6] + a0*Wn[0] + a1*Wn[3] + a2*Wn[6]);
    o.y = tanhf(bc[1] + x0*Ws[1] + x1*Ws[4] + x2*Ws[7] + a0*Wn[1] + a1*Wn[4] + a2*Wn[7]);
    o.z = tanhf(bc[2] + x0*Ws[2] + x1*Ws[5] + x2*Ws[8] + a0*Wn[2] + a1*Wn[5] + a2*Wn[8]);
    o.w = 0.f;
    g_h4[i] = o;
}

// ---------------- fully fused per-pathway kernel ----------------
__global__ void __launch_bounds__(NT, 1) k_path(
    const int*   __restrict__ pe,
    const float* __restrict__ subWl, const float* __restrict__ subbl,
    const float* __restrict__ subWr,
    const float* __restrict__ pWrel, const float* __restrict__ pWroot,
    const float* __restrict__ poolb,
    const float* __restrict__ gateW, const float* __restrict__ gateb,
    const float* __restrict__ linW,  const float* __restrict__ linb,
    const float* __restrict__ mlpW)
{
    extern __shared__ char sm[];
    unsigned* ukey  = (unsigned*)(sm);
    int*      keysh = (int*)     (sm + 80000);
    float4*   mv    = (float4*)  (sm + 96384);
    unsigned* hist  = (unsigned*)(sm + 161920);
    unsigned* sscan = (unsigned*)(sm + 194688);
    __shared__ unsigned s_bin, s_rem, s_cnt;
    __shared__ unsigned sredA[32], sredB[32];

    const int p    = blockIdx.x;
    const int tid  = threadIdx.x;
    const int lane = tid & 31;
    const int wid  = tid >> 5;

    float Wl[9], Wr[9];
#pragma unroll
    for (int q = 0; q < 9; q++) { Wl[q] = __ldg(subWl + 9*p + q); Wr[q] = __ldg(subWr + 9*p + q); }
    const float bl0 = __ldg(subbl+3*p), bl1 = __ldg(subbl+3*p+1), bl2 = __ldg(subbl+3*p+2);
    const float wr0 = __ldg(pWrel+3*p), wr1 = __ldg(pWrel+3*p+1), wr2 = __ldg(pWrel+3*p+2);
    const float wo0 = __ldg(pWroot+3*p), wo1 = __ldg(pWroot+3*p+1), wo2 = __ldg(pWroot+3*p+2);
    const float pb  = __ldg(poolb + p);
    const float gW0 = __ldg(gateW+3*p), gW1 = __ldg(gateW+3*p+1), gW2 = __ldg(gateW+3*p+2);
    const float gb  = __ldg(gateb + p);

    // phase 0: init hash
    for (int i = tid; i < HS; i += NT) {
        keysh[i] = 0;
        mv[i] = make_float4(0.f, 0.f, 0.f, 0.f);
    }
    __syncthreads();

    const int* ps = pe + p * 2 * EPE;
    const int* pd = ps + EPE;

    // phase 1: hash insert dst, accumulate msum/cnt (smem atomics)
    float* mvf = (float*)mv;
    for (int e = tid; e < EPE; e += NT) {
        int s = ps[e], d = pd[e];
        unsigned slot = ((unsigned)d * 2654435761u) >> 20;
        for (;;) {
            int prev = atomicCAS(&keysh[slot], 0, d + 1);
            if (prev == 0 || prev == d + 1) break;
            slot = (slot + 1) & HM;
        }
        float4 hv = g_h4[s];
        atomicAdd(&mvf[4*slot],   hv.x);
        atomicAdd(&mvf[4*slot+1], hv.y);
        atomicAdd(&mvf[4*slot+2], hv.z);
        atomicAdd(&mvf[4*slot+3], 1.f);
    }
    __syncthreads();

    // phase 1b: msum/cnt -> mean, w := 0 (arel accumulator)
    for (int slot = tid; slot < HS; slot += NT) {
        if (keysh[slot] != 0) {
            float4 v = mv[slot];
            float inv = 1.f / v.w;
            mv[slot] = make_float4(v.x * inv, v.y * inv, v.z * inv, 0.f);
        }
    }
    __syncthreads();

    // phase 2: arel[d] += xc(s) . Wrel
    for (int e = tid; e < EPE; e += NT) {
        int s = ps[e], d = pd[e];
        float4 hv = g_h4[s];
        float m0 = 0.f, m1 = 0.f, m2 = 0.f;
        int sl = hlookupS(s, keysh);
        if (sl >= 0) { float4 mm = mv[sl]; m0 = mm.x; m1 = mm.y; m2 = mm.z; }
        float xc0 = fmaxf(bl0 + hv.x*Wr[0] + hv.y*Wr[3] + hv.z*Wr[6] + m0*Wl[0] + m1*Wl[3] + m2*Wl[6], 0.f);
        float xc1 = fmaxf(bl1 + hv.x*Wr[1] + hv.y*Wr[4] + hv.z*Wr[7] + m0*Wl[1] + m1*Wl[4] + m2*Wl[7], 0.f);
        float xc2 = fmaxf(bl2 + hv.x*Wr[2] + hv.y*Wr[5] + hv.z*Wr[8] + m0*Wl[2] + m1*Wl[5] + m2*Wl[8], 0.f);
        float val = xc0*wr0 + xc1*wr1 + xc2*wr2;
        int sd = hlookupS(d, keysh);
        atomicAdd(&mvf[4*sd+3], val);
    }
    __syncthreads();

    // phase 3: score all nodes -> ukey (smem), track min/max
    unsigned mymin = 0xffffffffu, mymax = 0u;
    for (int i = tid; i < NN; i += NT) {
        float4 hv = g_h4[i];
        float m0 = 0.f, m1 = 0.f, m2 = 0.f, ar = 0.f;
        int sl = hlookupS(i, keysh);
        if (sl >= 0) { float4 mm = mv[sl]; m0 = mm.x; m1 = mm.y; m2 = mm.z; ar = mm.w; }
        float xc0 = fmaxf(bl0 + hv.x*Wr[0] + hv.y*Wr[3] + hv.z*Wr[6] + m0*Wl[0] + m1*Wl[3] + m2*Wl[6], 0.f);
        float xc1 = fmaxf(bl1 + hv.x*Wr[1] + hv.y*Wr[4] + hv.z*Wr[7] + m0*Wl[1] + m1*Wl[4] + m2*Wl[7], 0.f);
        float xc2 = fmaxf(bl2 + hv.x*Wr[2] + hv.y*Wr[5] + hv.z*Wr[8] + m0*Wl[2] + m1*Wl[5] + m2*Wl[8], 0.f);
        float sc = pb + ar + xc0*wo0 + xc1*wo1 + xc2*wo2;
        unsigned u = fkey(sc);
        ukey[i] = u;
        mymin = min(mymin, u); mymax = max(mymax, u);
    }
    mymin = __reduce_min_sync(0xffffffffu, mymin);
    mymax = __reduce_max_sync(0xffffffffu, mymax);
    if (lane == 0) { sredA[wid] = mymin; sredB[wid] = mymax; }
    __syncthreads();
    unsigned lo, hi;
    {
        unsigned mn = sredA[lane & 31], mx = sredB[lane & 31];
        // reduce 32 values in warp 0, then broadcast via shared
        if (wid == 0) {
            mn = __reduce_min_sync(0xffffffffu, sredA[lane]);
            mx = __reduce_max_sync(0xffffffffu, sredB[lane]);
            if (lane == 0) { sredA[0] = mn; sredB[0] = mx; }
        }
        __syncthreads();
        lo = sredA[0]; hi = sredB[0];
    }

    // phase 4: adaptive radix select (descending rank KKEEP), exact
    unsigned rem = KKEEP, ceq = NN;
    while (lo < hi) {
        unsigned long long width = (unsigned long long)(hi - lo) + 1ull;
        int bits = 64 - __clzll((long long)(width - 1ull));
        int shift = bits > 13 ? bits - 13 : 0;
        for (int b = tid; b < NB; b += NT) hist[b] = 0;
        __syncthreads();
        for (int it = 0; it < NITER; it++) {
            int i = it * NT + tid;
            unsigned bin = 0xffffffffu;
            if (i < NN) {
                unsigned u = ukey[i];
                if (u >= lo && u <= hi) bin = (u - lo) >> shift;
            }
            unsigned msk = __match_any_sync(0xffffffffu, bin);
            if (bin != 0xffffffffu && (__ffs(msk) - 1) == lane)
                atomicAdd(&hist[bin], __popc(msk));
        }
        __syncthreads();
        unsigned psum = 0;
#pragma unroll
        for (int q = 0; q < NB/NT; q++) psum += hist[tid*(NB/NT)+q];
        sscan[tid] = psum; __syncthreads();
        for (int d = 1; d < NT; d <<= 1) {
            unsigned v = sscan[tid] + ((tid + d < NT) ? sscan[tid + d] : 0);
            __syncthreads(); sscan[tid] = v; __syncthreads();
        }
        unsigned c = (tid + 1 < NT) ? sscan[tid + 1] : 0;   // count above my chunk
        for (int q = NB/NT - 1; q >= 0; q--) {
            int b = tid*(NB/NT) + q;
            unsigned hc = hist[b];
            if (c < rem && c + hc >= rem) { s_bin = b; s_cnt = hc; s_rem = rem - c; }
            c += hc;
        }
        __syncthreads();
        unsigned bin = s_bin; rem = s_rem; ceq = s_cnt;
        unsigned nlo = lo + (bin << shift);
        unsigned long long nhi64 = (unsigned long long)nlo + (1ull << shift) - 1ull;
        hi = (nhi64 > (unsigned long long)hi) ? hi : (unsigned)nhi64;
        lo = nlo;
        __syncthreads();
    }
    const unsigned Tu = lo;
    unsigned Itie = NN;

    if (rem < ceq) {
        // tie-break: rem-th smallest index among {i : ukey[i]==Tu}
        unsigned lo2 = 0, hi2 = NN - 1;
        while (lo2 < hi2) {
            unsigned long long width = (unsigned long long)(hi2 - lo2) + 1ull;
            int bits = 64 - __clzll((long long)(width - 1ull));
            int shift = bits > 13 ? bits - 13 : 0;
            for (int b = tid; b < NB; b += NT) hist[b] = 0;
            __syncthreads();
            for (int it = 0; it < NITER; it++) {
                int i = it * NT + tid;
                unsigned bin = 0xffffffffu;
                if (i < NN && ukey[i] == Tu && (unsigned)i >= lo2 && (unsigned)i <= hi2)
                    bin = ((unsigned)i - lo2) >> shift;
                unsigned msk = __match_any_sync(0xffffffffu, bin);
                if (bin != 0xffffffffu && (__ffs(msk) - 1) == lane)
                    atomicAdd(&hist[bin], __popc(msk));
            }
            __syncthreads();
            unsigned psum = 0;
#pragma unroll
            for (int q = 0; q < NB/NT; q++) psum += hist[tid*(NB/NT)+q];
            sscan[tid] = psum; __syncthreads();
            for (int d = 1; d < NT; d <<= 1) {
                unsigned v = sscan[tid] + ((tid >= d) ? sscan[tid - d] : 0);
                __syncthreads(); sscan[tid] = v; __syncthreads();
            }
            unsigned c = sscan[tid] - psum;   // count below my chunk
            for (int q = 0; q < NB/NT; q++) {
                int b = tid*(NB/NT) + q;
                unsigned hc = hist[b];
                if (c < rem && c + hc >= rem) { s_bin = b; s_rem = rem - c; }
                c += hc;
            }
            __syncthreads();
            unsigned bin = s_bin; rem = s_rem;
            unsigned nlo = lo2 + (bin << shift);
            unsigned long long nhi64 = (unsigned long long)nlo + (1ull << shift) - 1ull;
            hi2 = (nhi64 > (unsigned long long)hi2) ? hi2 : (unsigned)nhi64;
            lo2 = nlo;
            __syncthreads();
        }
        Itie = lo2;
    }

    // phase 5: fused softmax readout over kept nodes (recompute xk; sc from ukey)
    float ssum = 0.f, a0 = 0.f, a1 = 0.f, a2 = 0.f;
    for (int i = tid; i < NN; i += NT) {
        unsigned u = ukey[i];
        bool kept = (u > Tu) || (u == Tu && (unsigned)i <= Itie);
        if (!kept) continue;
        float4 hv = g_h4[i];
        float m0 = 0.f, m1 = 0.f, m2 = 0.f;
        int sl = hlookupS(i, keysh);
        if (sl >= 0) { float4 mm = mv[sl]; m0 = mm.x; m1 = mm.y; m2 = mm.z; }
        float xc0 = fmaxf(bl0 + hv.x*Wr[0] + hv.y*Wr[3] + hv.z*Wr[6] + m0*Wl[0] + m1*Wl[3] + m2*Wl[6], 0.f);
        float xc1 = fmaxf(bl1 + hv.x*Wr[1] + hv.y*Wr[4] + hv.z*Wr[7] + m0*Wl[1] + m1*Wl[4] + m2*Wl[7], 0.f);
        float xc2 = fmaxf(bl2 + hv.x*Wr[2] + hv.y*Wr[5] + hv.z*Wr[8] + m0*Wl[2] + m1*Wl[5] + m2*Wl[8], 0.f);
        float sc = unfkey(u);
        float e2 = __expf(2.f * sc);
        float tv = 1.f - 2.f / (e2 + 1.f);            // tanh(sc)
        float xk0 = xc0*tv, xk1 = xc1*tv, xk2 = xc2*tv;
        float l = gb + xk0*gW0 + xk1*gW1 + xk2*gW2;
        float e = __expf(l);
        ssum += e; a0 += e*xk0; a1 += e*xk1; a2 += e*xk2;
    }
#pragma unroll
    for (int off = 16; off > 0; off >>= 1) {
        ssum += __shfl_down_sync(0xffffffffu, ssum, off);
        a0   += __shfl_down_sync(0xffffffffu, a0, off);
        a1   += __shfl_down_sync(0xffffffffu, a1, off);
        a2   += __shfl_down_sync(0xffffffffu, a2, off);
    }
    __syncthreads();
    float* red = (float*)hist;
    if (lane == 0) { red[wid] = ssum; red[32+wid] = a0; red[64+wid] = a1; red[96+wid] = a2; }
    __syncthreads();
    if (tid == 0) {
        float S = 0.f, A0 = 0.f, A1 = 0.f, A2 = 0.f;
#pragma unroll
        for (int q = 0; q < 32; q++) { S += red[q]; A0 += red[32+q]; A1 += red[64+q]; A2 += red[96+q]; }
        float inv = 1.f / S;
        float v0 = fmaxf(A0 * inv, 0.f);
        float v1 = fmaxf(A1 * inv, 0.f);
        float v2 = fmaxf(A2 * inv, 0.f);
        float rr = fmaxf(v0 * __ldg(linW) + v1 * __ldg(linW+1) + v2 * __ldg(linW+2) + __ldg(linb), 0.f);
        g_pathC[p] = rr * __ldg(mlpW + p);
    }
}

__global__ void k_out(const float* __restrict__ mlpb, float* __restrict__ out) {
    __shared__ float sbuf[256];
    int tid = threadIdx.x;
    float v = 0.f;
    for (int i = tid; i < PP; i += 256) v += g_pathC[i];
    sbuf[tid] = v;
    __syncthreads();
    for (int s = 128; s > 0; s >>= 1) { if (tid < s) sbuf[tid] += sbuf[tid + s]; __syncthreads(); }
    if (tid == 0) out[0] = 1.f / (1.f + expf(-(sbuf[0] + mlpb[0])));
}

// ---------------- launch ----------------
extern "C" void kernel_launch(void* const* d_in, const int* in_sizes, int n_in,
                              void* d_out, int out_size) {
    const float* x          = (const float*)d_in[0];
    const int*   edge_index = (const int*)  d_in[1];
    const int*   path_edges = (const int*)  d_in[2];
    const float* W_pool     = (const float*)d_in[3];
    const float* b_pool     = (const float*)d_in[4];
    const float* W_self     = (const float*)d_in[5];
    const float* W_neigh    = (const float*)d_in[6];
    const float* b_conv     = (const float*)d_in[7];
    const float* sub_Wl     = (const float*)d_in[8];
    const float* sub_bl     = (const float*)d_in[9];
    const float* sub_Wr     = (const float*)d_in[10];
    const float* pool_Wrel  = (const float*)d_in[11];
    const float* pool_Wroot = (const float*)d_in[12];
    const float* pool_b     = (const float*)d_in[13];
    const float* gate_W     = (const float*)d_in[14];
    const float* gate_b     = (const float*)d_in[15];
    const float* lin_W      = (const float*)d_in[16];
    const float* lin_b      = (const float*)d_in[17];
    const float* mlp_W      = (const float*)d_in[18];
    const float* mlp_b      = (const float*)d_in[19];
    float* out = (float*)d_out;

    cudaFuncSetAttribute(k_path, cudaFuncAttributeMaxDynamicSharedMemorySize, SMEM_BYTES);

    k_hp     <<<(NN + 255) / 256, 256>>>(x, W_pool, b_pool);
    k_segmax <<<(EE + 511) / 512, 512>>>(edge_index);
    k_h      <<<(NN + 255) / 256, 256>>>(x, W_self, W_neigh, b_conv);
    k_path   <<<PP, NT, SMEM_BYTES>>>(path_edges, sub_Wl, sub_bl, sub_Wr,
                                      pool_Wrel, pool_Wroot, pool_b,
                                      gate_W, gate_b, lin_W, lin_b, mlp_W);
    k_out    <<<1, 256>>>(mlp_b, out);
}

// round 5
// speedup vs baseline: 1.8330x; 1.2782x over previous
#include <cuda_runtime.h>
#include <stdint.h>

#define NN    20000
#define EE    200000
#define PP    300
#define EPE   2000
#define KKEEP 16000
#define HS    4096
#define HM    4095
#define NB    8192      // bins per histogram copy
#define NT    1024
#define NITER 20        // ceil(NN/NT)

// dynamic smem layout (bytes):
//   ukey : 20000 u32        [0,      80000)
//   keysh: 4096  int        [80000,  96384)
//   val  : 4096  int        [96384, 112768)
//   mv   : 2048  float4     [112768,145536)
//   hist : 2*8192 u32       [145536,211072)
#define SMEM_BYTES 211072

__device__ float4 g_h4[NN];
__device__ float  g_hp[NN * 3];
__device__ float  g_agg[NN * 3];
__device__ float  g_pathC[PP];

__device__ __forceinline__ unsigned fkey(float f) {
    unsigned u = __float_as_uint(f);
    return (u & 0x80000000u) ? ~u : (u | 0x80000000u);
}

// MUFU-free fast paths (explicit fmaf chains -> bit-identical across call sites)
__device__ __forceinline__ float tanh_fast(float x) {
    float a = fabsf(x);
    if (a < 0.53f) {
        float x2 = x * x;
        float p = fmaf(x2, -5.3968254e-2f, 1.3333333e-1f);
        p = fmaf(x2, p, -3.3333333e-1f);
        p = fmaf(x2, p, 1.0f);
        return x * p;
    }
    return tanhf(x);
}
__device__ __forceinline__ float exp_fast(float t) {
    if (fabsf(t) < 0.3f) {
        float p = fmaf(t, 4.1666668e-2f, 1.6666667e-1f);
        p = fmaf(t, p, 0.5f);
        p = fmaf(t, p, 1.0f);
        p = fmaf(t, p, 1.0f);
        return p;
    }
    return __expf(t);
}

// shared node value computation (explicit fmaf everywhere)
__device__ __forceinline__ void node_val(
    float4 hv, float m0, float m1, float m2, float ar,
    const float* Wl, const float* Wr,
    float bl0, float bl1, float bl2,
    float wo0, float wo1, float wo2, float pb,
    float gW0, float gW1, float gW2,
    unsigned& u, float& e, float& k0, float& k1, float& k2)
{
    float t0 = fmaf(hv.x, Wr[0], fmaf(hv.y, Wr[3], fmaf(hv.z, Wr[6], bl0)));
    float t1 = fmaf(hv.x, Wr[1], fmaf(hv.y, Wr[4], fmaf(hv.z, Wr[7], bl1)));
    float t2 = fmaf(hv.x, Wr[2], fmaf(hv.y, Wr[5], fmaf(hv.z, Wr[8], bl2)));
    float xc0 = fmaxf(fmaf(m0, Wl[0], fmaf(m1, Wl[3], fmaf(m2, Wl[6], t0))), 0.f);
    float xc1 = fmaxf(fmaf(m0, Wl[1], fmaf(m1, Wl[4], fmaf(m2, Wl[7], t1))), 0.f);
    float xc2 = fmaxf(fmaf(m0, Wl[2], fmaf(m1, Wl[5], fmaf(m2, Wl[8], t2))), 0.f);
    float sc = fmaf(xc0, wo0, fmaf(xc1, wo1, fmaf(xc2, wo2, pb + ar)));
    u = fkey(sc);
    float tv = tanh_fast(sc);
    k0 = xc0 * tv; k1 = xc1 * tv; k2 = xc2 * tv;
    float l = fmaf(k0, gW0, fmaf(k1, gW1, k2 * gW2));   // gb dropped: cancels in softmax
    e = exp_fast(l);
}

// ---------------- global stage ----------------
__global__ void k_hp(const float* __restrict__ x, const float* __restrict__ Wp,
                     const float* __restrict__ bp) {
    int i = blockIdx.x * blockDim.x + threadIdx.x;
    if (i >= NN) return;
    float x0 = x[3*i], x1 = x[3*i+1], x2 = x[3*i+2];
#pragma unroll
    for (int c = 0; c < 3; c++) {
        float v = fmaxf(bp[c] + x0*Wp[c] + x1*Wp[3+c] + x2*Wp[6+c], 0.f);
        g_hp[3*i+c] = v;
        g_agg[3*i+c] = v;
    }
}

__global__ void k_segmax(const int* __restrict__ ei) {
    int e = blockIdx.x * blockDim.x + threadIdx.x;
    if (e >= EE) return;
    int s = ei[e], d = ei[EE + e];
#pragma unroll
    for (int c = 0; c < 3; c++)
        atomicMax((int*)&g_agg[3*d+c], __float_as_int(g_hp[3*s+c]));
}

__global__ void k_h(const float* __restrict__ x, const float* __restrict__ Ws,
                    const float* __restrict__ Wn, const float* __restrict__ bc) {
    int i = blockIdx.x * blockDim.x + threadIdx.x;
    if (i >= NN) return;
    float x0 = x[3*i], x1 = x[3*i+1], x2 = x[3*i+2];
    float a0 = g_agg[3*i], a1 = g_agg[3*i+1], a2 = g_agg[3*i+2];
    float4 o;
    o.x = tanhf(bc[0] + x0*Ws[0] + x1*Ws[3] + x2*Ws[6] + a0*Wn[0] + a1*Wn[3] + a2*Wn[6]);
    o.y = tanhf(bc[1] + x0*Ws[1] + x1*Ws[4] + x2*Ws[7] + a0*Wn[1] + a1*Wn[4] + a2*Wn[7]);
    o.z = tanhf(bc[2] + x0*Ws[2] + x1*Ws[5] + x2*Ws[8] + a0*Wn[2] + a1*Wn[5] + a2*Wn[8]);
    o.w = 0.f;
    g_h4[i] = o;
}

// ---------------- fully fused per-pathway kernel ----------------
__global__ void __launch_bounds__(NT, 1) k_path(
    const int*   __restrict__ pe,
    const float* __restrict__ subWl, const float* __restrict__ subbl,
    const float* __restrict__ subWr,
    const float* __restrict__ pWrel, const float* __restrict__ pWroot,
    const float* __restrict__ poolb,
    const float* __restrict__ gateW, const float* __restrict__ gateb,
    const float* __restrict__ linW,  const float* __restrict__ linb,
    const float* __restrict__ mlpW)
{
    extern __shared__ char sm[];
    unsigned* ukey  = (unsigned*)(sm);
    int*      keysh = (int*)     (sm + 80000);
    int*      val   = (int*)     (sm + 96384);
    float4*   mv    = (float4*)  (sm + 112768);
    unsigned* hist  = (unsigned*)(sm + 145536);

    __shared__ unsigned s_wa[32], s_wb[32];
    __shared__ unsigned s_bin, s_rem, s_cnt, s_itie, s_dn, s_tot;
    __shared__ float    fred[128];

    const int p    = blockIdx.x;
    const int tid  = threadIdx.x;
    const int lane = tid & 31;
    const int wid  = tid >> 5;

    float Wl[9], Wr[9];
#pragma unroll
    for (int q = 0; q < 9; q++) { Wl[q] = __ldg(subWl + 9*p + q); Wr[q] = __ldg(subWr + 9*p + q); }
    const float bl0 = __ldg(subbl+3*p), bl1 = __ldg(subbl+3*p+1), bl2 = __ldg(subbl+3*p+2);
    const float wr0 = __ldg(pWrel+3*p), wr1 = __ldg(pWrel+3*p+1), wr2 = __ldg(pWrel+3*p+2);
    const float wo0 = __ldg(pWroot+3*p), wo1 = __ldg(pWroot+3*p+1), wo2 = __ldg(pWroot+3*p+2);
    const float pb  = __ldg(poolb + p);
    const float gW0 = __ldg(gateW+3*p), gW1 = __ldg(gateW+3*p+1), gW2 = __ldg(gateW+3*p+2);

    // ---- phase 0: init keys + mv ----
    ((int4*)keysh)[tid] = make_int4(0, 0, 0, 0);
    float4 z4 = make_float4(0.f, 0.f, 0.f, 0.f);
    mv[tid] = z4; mv[tid + NT] = z4;
    __syncthreads();

    const int* ps = pe + p * 2 * EPE;
    const int* pd = ps + EPE;
    const int e0 = tid, e1 = tid + NT;
    int slotA = -1, slotB = -1;

    // ---- phase 1a: CAS-insert dst keys (cache slots) ----
    if (e0 < EPE) {
        int d = pd[e0];
        unsigned slot = ((unsigned)d * 2654435761u) >> 20;
        for (;;) {
            int prev = atomicCAS(&keysh[slot], 0, d + 1);
            if (prev == 0 || prev == d + 1) break;
            slot = (slot + 1) & HM;
        }
        slotA = (int)slot;
    }
    if (e1 < EPE) {
        int d = pd[e1];
        unsigned slot = ((unsigned)d * 2654435761u) >> 20;
        for (;;) {
            int prev = atomicCAS(&keysh[slot], 0, d + 1);
            if (prev == 0 || prev == d + 1) break;
            slot = (slot + 1) & HM;
        }
        slotB = (int)slot;
    }
    __syncthreads();

    // ---- phase 1b: deterministic compaction: val[slot] = dense index ----
    {
        int4 kk = ((int4*)keysh)[tid];
        unsigned c = (kk.x != 0) + (kk.y != 0) + (kk.z != 0) + (kk.w != 0);
        unsigned v = c;
#pragma unroll
        for (int d = 1; d < 32; d <<= 1) { unsigned t = __shfl_up_sync(~0u, v, d); if (lane >= d) v += t; }
        if (lane == 31) s_wa[wid] = v;
        __syncthreads();
        if (wid == 0) {
            unsigned x = s_wa[lane];
#pragma unroll
            for (int d = 1; d < 32; d <<= 1) { unsigned t = __shfl_up_sync(~0u, x, d); if (lane >= d) x += t; }
            s_wb[lane] = x;
        }
        __syncthreads();
        unsigned excl = (v - c) + ((wid > 0) ? s_wb[wid - 1] : 0u);
        int b = (int)excl;
        if (kk.x) val[4*tid]   = b++;
        if (kk.y) val[4*tid+1] = b++;
        if (kk.z) val[4*tid+2] = b++;
        if (kk.w) val[4*tid+3] = b++;
        if (tid == NT - 1) s_tot = excl + c;
    }
    __syncthreads();

    // ---- phase 1c: accumulate msum/cnt into compacted mv ----
    float* mvf = (float*)mv;
    int idxA = (slotA >= 0) ? val[slotA] : -1;
    int idxB = (slotB >= 0) ? val[slotB] : -1;
    if (e0 < EPE) {
        float4 hv = g_h4[ps[e0]];
        atomicAdd(&mvf[4*idxA],   hv.x);
        atomicAdd(&mvf[4*idxA+1], hv.y);
        atomicAdd(&mvf[4*idxA+2], hv.z);
        atomicAdd(&mvf[4*idxA+3], 1.f);
    }
    if (e1 < EPE) {
        float4 hv = g_h4[ps[e1]];
        atomicAdd(&mvf[4*idxB],   hv.x);
        atomicAdd(&mvf[4*idxB+1], hv.y);
        atomicAdd(&mvf[4*idxB+2], hv.z);
        atomicAdd(&mvf[4*idxB+3], 1.f);
    }
    __syncthreads();

    // ---- phase 1d: normalize mean, zero arel ----
    {
        int tot = (int)s_tot;
        for (int idx = tid; idx < tot; idx += NT) {
            float4 v = mv[idx];
            float inv = 1.f / v.w;
            mv[idx] = make_float4(v.x * inv, v.y * inv, v.z * inv, 0.f);
        }
    }
    __syncthreads();

    // ---- phase 2: arel[d] += xc(s) . Wrel ----
#pragma unroll
    for (int ee = 0; ee < 2; ee++) {
        int e = (ee == 0) ? e0 : e1;
        int myidx = (ee == 0) ? idxA : idxB;
        if (e < EPE) {
            int s = ps[e];
            float4 hv = g_h4[s];
            float m0 = 0.f, m1 = 0.f, m2 = 0.f;
            // lookup s
            unsigned slot = ((unsigned)s * 2654435761u) >> 20;
            int want = s + 1;
            for (;;) {
                int k2 = keysh[slot];
                if (k2 == want) { float4 mm = mv[val[slot]]; m0 = mm.x; m1 = mm.y; m2 = mm.z; break; }
                if (k2 == 0) break;
                slot = (slot + 1) & HM;
            }
            float xc0 = fmaxf(fmaf(m0, Wl[0], fmaf(m1, Wl[3], fmaf(m2, Wl[6], fmaf(hv.x, Wr[0], fmaf(hv.y, Wr[3], fmaf(hv.z, Wr[6], bl0)))))), 0.f);
            float xc1 = fmaxf(fmaf(m0, Wl[1], fmaf(m1, Wl[4], fmaf(m2, Wl[7], fmaf(hv.x, Wr[1], fmaf(hv.y, Wr[4], fmaf(hv.z, Wr[7], bl1)))))), 0.f);
            float xc2 = fmaxf(fmaf(m0, Wl[2], fmaf(m1, Wl[5], fmaf(m2, Wl[8], fmaf(hv.x, Wr[2], fmaf(hv.y, Wr[5], fmaf(hv.z, Wr[8], bl2)))))), 0.f);
            float vv = fmaf(xc0, wr0, fmaf(xc1, wr1, xc2 * wr2));
            atomicAdd(&mvf[4*myidx+3], vv);
        }
    }
    __syncthreads();

    // ---- phase 3: score all nodes (non-member form), accumulate all-sums ----
    float ssum = 0.f, a0 = 0.f, a1 = 0.f, a2 = 0.f;
    unsigned mymin = 0xffffffffu, mymax = 0u;
    for (int i = tid; i < NN; i += NT) {
        float4 hv = g_h4[i];
        unsigned u; float e, k0, k1, k2;
        node_val(hv, 0.f, 0.f, 0.f, 0.f, Wl, Wr, bl0, bl1, bl2,
                 wo0, wo1, wo2, pb, gW0, gW1, gW2, u, e, k0, k1, k2);
        ukey[i] = u;
        mymin = min(mymin, u); mymax = max(mymax, u);
        ssum += e;
        a0 = fmaf(e, k0, a0); a1 = fmaf(e, k1, a1); a2 = fmaf(e, k2, a2);
    }
    __syncthreads();   // all ukey writes done before member overwrite

    // ---- phase 4: member fixup (overwrite ukey, delta-adjust sums) ----
    for (int slot = tid; slot < HS; slot += NT) {
        int kk = keysh[slot];
        if (kk != 0) {
            int d = kk - 1;
            float4 mm = mv[val[slot]];
            float4 hv = g_h4[d];
            unsigned uo; float eo, o0, o1, o2;
            node_val(hv, 0.f, 0.f, 0.f, 0.f, Wl, Wr, bl0, bl1, bl2,
                     wo0, wo1, wo2, pb, gW0, gW1, gW2, uo, eo, o0, o1, o2);
            unsigned un; float en, n0, n1, n2;
            node_val(hv, mm.x, mm.y, mm.z, mm.w, Wl, Wr, bl0, bl1, bl2,
                     wo0, wo1, wo2, pb, gW0, gW1, gW2, un, en, n0, n1, n2);
            ukey[d] = un;
            mymin = min(mymin, un); mymax = max(mymax, un);
            ssum += en - eo;
            a0 += en*n0 - eo*o0; a1 += en*n1 - eo*o1; a2 += en*n2 - eo*o2;
        }
    }

    // ---- block min/max reduce ----
    mymin = __reduce_min_sync(0xffffffffu, mymin);
    mymax = __reduce_max_sync(0xffffffffu, mymax);
    if (lane == 0) { s_wa[wid] = mymin; s_wb[wid] = mymax; }
    __syncthreads();
    if (wid == 0) {
        unsigned mn = __reduce_min_sync(0xffffffffu, s_wa[lane]);
        unsigned mx = __reduce_max_sync(0xffffffffu, s_wb[lane]);
        if (lane == 0) { s_wa[0] = mn; s_wb[0] = mx; }
    }
    __syncthreads();
    unsigned lo = s_wa[0], hi = s_wb[0];
    __syncthreads();

    // ---- phase 5: adaptive radix select (descending rank KKEEP), 2-copy hist ----
    unsigned rem = KKEEP, ceq = NN;
    while (lo < hi) {
        unsigned width = hi - lo;                 // >= 1
        int bits = 32 - __clz(width);
        int shift = bits > 13 ? bits - 13 : 0;
        uint4 zz = make_uint4(0, 0, 0, 0);
        ((uint4*)hist)[tid]        = zz;
        ((uint4*)hist)[NT + tid]   = zz;
        ((uint4*)hist)[2*NT + tid] = zz;
        ((uint4*)hist)[3*NT + tid] = zz;
        __syncthreads();
        unsigned* myh = hist + ((wid & 1) ? NB : 0);
        for (int it = 0; it < NITER; it++) {
            int i = it * NT + tid;
            unsigned bin = 0xffffffffu;
            if (i < NN) {
                unsigned u = ukey[i];
                if (u >= lo && u <= hi) bin = (u - lo) >> shift;
            }
            unsigned msk = __match_any_sync(0xffffffffu, bin);
            if (bin != 0xffffffffu && (__ffs(msk) - 1) == lane)
                atomicAdd(&myh[bin], __popc(msk));
        }
        __syncthreads();
        uint4 c0a = ((uint4*)hist)[tid*2], c0b = ((uint4*)hist)[tid*2+1];
        uint4 c1a = ((uint4*)(hist + NB))[tid*2], c1b = ((uint4*)(hist + NB))[tid*2+1];
        unsigned bt[8] = { c0a.x+c1a.x, c0a.y+c1a.y, c0a.z+c1a.z, c0a.w+c1a.w,
                           c0b.x+c1b.x, c0b.y+c1b.y, c0b.z+c1b.z, c0b.w+c1b.w };
        unsigned psum = bt[0]+bt[1]+bt[2]+bt[3]+bt[4]+bt[5]+bt[6]+bt[7];
        unsigned v = psum;
#pragma unroll
        for (int d = 1; d < 32; d <<= 1) { unsigned t = __shfl_down_sync(~0u, v, d); if (lane + d < 32) v += t; }
        if (lane == 0) s_wa[wid] = v;
        __syncthreads();
        if (wid == 0) {
            unsigned x = s_wa[lane];
#pragma unroll
            for (int d = 1; d < 32; d <<= 1) { unsigned t = __shfl_down_sync(~0u, x, d); if (lane + d < 32) x += t; }
            s_wb[lane] = x;
        }
        __syncthreads();
        unsigned c = ((wid < 31) ? s_wb[wid + 1] : 0u) + (v - psum);
#pragma unroll
        for (int q = 7; q >= 0; q--) {
            unsigned hc = bt[q];
            if (c < rem && c + hc >= rem) { s_bin = tid*8 + q; s_cnt = hc; s_rem = rem - c; }
            c += hc;
        }
        __syncthreads();
        unsigned bin = s_bin; rem = s_rem; ceq = s_cnt;
        unsigned nlo = lo + (bin << shift);
        unsigned long long nh = (unsigned long long)nlo + ((shift > 0) ? ((1ull << shift) - 1ull) : 0ull);
        hi = (nh > (unsigned long long)hi) ? hi : (unsigned)nh;
        lo = nlo;
        __syncthreads();
    }
    const unsigned Tu = lo;
    unsigned Itie = NN;

    // ---- phase 6: single-pass index tie-break ----
    if (rem < ceq) {
        hist[tid] = 0; hist[NB + tid] = 0;       // 625 bins used, zero 1024 per copy
        __syncthreads();
        unsigned* myh = hist + ((wid & 1) ? NB : 0);
        for (int it = 0; it < NITER; it++) {
            int i = it * NT + tid;
            unsigned bin = 0xffffffffu;
            if (i < NN && ukey[i] == Tu) bin = (unsigned)i >> 5;
            unsigned msk = __match_any_sync(0xffffffffu, bin);
            if (bin != 0xffffffffu && (__ffs(msk) - 1) == lane)
                atomicAdd(&myh[bin], __popc(msk));
        }
        __syncthreads();
        unsigned psum = (tid < 625) ? (hist[tid] + hist[NB + tid]) : 0u;
        unsigned v = psum;
#pragma unroll
        for (int d = 1; d < 32; d <<= 1) { unsigned t = __shfl_up_sync(~0u, v, d); if (lane >= d) v += t; }
        if (lane == 31) s_wa[wid] = v;
        __syncthreads();
        if (wid == 0) {
            unsigned x = s_wa[lane];
#pragma unroll
            for (int d = 1; d < 32; d <<= 1) { unsigned t = __shfl_up_sync(~0u, x, d); if (lane >= d) x += t; }
            s_wb[lane] = x;
        }
        __syncthreads();
        unsigned below = (v - psum) + ((wid > 0) ? s_wb[wid - 1] : 0u);
        if (tid < 625 && below < rem && below + psum >= rem) { s_bin = tid; s_rem = rem - below; }
        __syncthreads();
        int bA = (int)s_bin; unsigned r2 = s_rem;
        if (wid == 0) {
            int i = bA * 32 + lane;
            bool f = (i < NN) && (ukey[i] == Tu);
            unsigned m = __ballot_sync(0xffffffffu, f);
            unsigned rk = __popc(m & ((1u << lane) - 1u)) + 1u;
            if (f && rk == r2) s_itie = (unsigned)i;
        }
        __syncthreads();
        Itie = s_itie;
    }

    // ---- phase 7: compact dropped nodes into hist region ----
    if (tid == 0) s_dn = 0;
    __syncthreads();
    int* dl = (int*)hist;
    for (int it = 0; it < NITER; it++) {
        int i = it * NT + tid;
        bool dr = false;
        if (i < NN) {
            unsigned u = ukey[i];
            dr = !((u > Tu) || (u == Tu && (unsigned)i <= Itie));
        }
        unsigned m = __ballot_sync(0xffffffffu, dr);
        if (m) {
            int leader = __ffs(m) - 1;
            unsigned base = 0;
            if (lane == leader) base = atomicAdd(&s_dn, __popc(m));
            base = __shfl_sync(0xffffffffu, base, leader);
            if (dr) dl[base + __popc(m & ((1u << lane) - 1u))] = i;
        }
    }
    __syncthreads();

    // ---- phase 8: subtract dropped contributions ----
    {
        int D = (int)s_dn;
        for (int k = tid; k < D; k += NT) {
            int i = dl[k];
            float4 hv = g_h4[i];
            float m0 = 0.f, m1 = 0.f, m2 = 0.f, ar = 0.f;
            unsigned slot = ((unsigned)i * 2654435761u) >> 20;
            int want = i + 1;
            for (;;) {
                int k2 = keysh[slot];
                if (k2 == want) { float4 mm = mv[val[slot]]; m0 = mm.x; m1 = mm.y; m2 = mm.z; ar = mm.w; break; }
                if (k2 == 0) break;
                slot = (slot + 1) & HM;
            }
            unsigned uu; float e, k0, k1, k2v;
            node_val(hv, m0, m1, m2, ar, Wl, Wr, bl0, bl1, bl2,
                     wo0, wo1, wo2, pb, gW0, gW1, gW2, uu, e, k0, k1, k2v);
            ssum -= e;
            a0 -= e * k0; a1 -= e * k1; a2 -= e * k2v;
        }
    }

    // ---- phase 9: final reduction + output ----
#pragma unroll
    for (int off = 16; off > 0; off >>= 1) {
        ssum += __shfl_down_sync(0xffffffffu, ssum, off);
        a0   += __shfl_down_sync(0xffffffffu, a0, off);
        a1   += __shfl_down_sync(0xffffffffu, a1, off);
        a2   += __shfl_down_sync(0xffffffffu, a2, off);
    }
    if (lane == 0) { fred[wid] = ssum; fred[32+wid] = a0; fred[64+wid] = a1; fred[96+wid] = a2; }
    __syncthreads();
    if (tid == 0) {
        float S = 0.f, A0 = 0.f, A1 = 0.f, A2 = 0.f;
#pragma unroll
        for (int q = 0; q < 32; q++) { S += fred[q]; A0 += fred[32+q]; A1 += fred[64+q]; A2 += fred[96+q]; }
        float inv = 1.f / S;
        float v0 = fmaxf(A0 * inv, 0.f);
        float v1 = fmaxf(A1 * inv, 0.f);
        float v2 = fmaxf(A2 * inv, 0.f);
        float rr = fmaxf(v0 * __ldg(linW) + v1 * __ldg(linW+1) + v2 * __ldg(linW+2) + __ldg(linb), 0.f);
        g_pathC[p] = rr * __ldg(mlpW + p);
    }
}

__global__ void k_out(const float* __restrict__ mlpb, float* __restrict__ out) {
    __shared__ float sbuf[256];
    int tid = threadIdx.x;
    float v = 0.f;
    for (int i = tid; i < PP; i += 256) v += g_pathC[i];
    sbuf[tid] = v;
    __syncthreads();
    for (int s = 128; s > 0; s >>= 1) { if (tid < s) sbuf[tid] += sbuf[tid + s]; __syncthreads(); }
    if (tid == 0) out[0] = 1.f / (1.f + expf(-(sbuf[0] + mlpb[0])));
}

// ---------------- launch ----------------
extern "C" void kernel_launch(void* const* d_in, const int* in_sizes, int n_in,
                              void* d_out, int out_size) {
    const float* x          = (const float*)d_in[0];
    const int*   edge_index = (const int*)  d_in[1];
    const int*   path_edges = (const int*)  d_in[2];
    const float* W_pool     = (const float*)d_in[3];
    const float* b_pool     = (const float*)d_in[4];
    const float* W_self     = (const float*)d_in[5];
    const float* W_neigh    = (const float*)d_in[6];
    const float* b_conv     = (const float*)d_in[7];
    const float* sub_Wl     = (const float*)d_in[8];
    const float* sub_bl     = (const float*)d_in[9];
    const float* sub_Wr     = (const float*)d_in[10];
    const float* pool_Wrel  = (const float*)d_in[11];
    const float* pool_Wroot = (const float*)d_in[12];
    const float* pool_b     = (const float*)d_in[13];
    const float* gate_W     = (const float*)d_in[14];
    const float* gate_b     = (const float*)d_in[15];
    const float* lin_W      = (const float*)d_in[16];
    const float* lin_b      = (const float*)d_in[17];
    const float* mlp_W      = (const float*)d_in[18];
    const float* mlp_b      = (const float*)d_in[19];
    float* out = (float*)d_out;
    (void)gate_b;  // constant gate bias cancels in softmax

    cudaFuncSetAttribute(k_path, cudaFuncAttributeMaxDynamicSharedMemorySize, SMEM_BYTES);

    k_hp     <<<(NN + 255) / 256, 256>>>(x, W_pool, b_pool);
    k_segmax <<<(EE + 511) / 512, 512>>>(edge_index);
    k_h      <<<(NN + 255) / 256, 256>>>(x, W_self, W_neigh, b_conv);
    k_path   <<<PP, NT, SMEM_BYTES>>>(path_edges, sub_Wl, sub_bl, sub_Wr,
                                      pool_Wrel, pool_Wroot, pool_b,
                                      gate_W, gate_b, lin_W, lin_b, mlp_W);
    k_out    <<<1, 256>>>(mlp_b, out);
}